// round 1
// baseline (speedup 1.0000x reference)
#include <cuda_runtime.h>
#include <cstdint>

#define NN 100000
#define EE 3200000
#define FF 10
#define HH 20
#define GG 512

// ---------------- device scratch (no allocation allowed) ----------------
__device__ __align__(256) float g_h1[NN * HH];
__device__ __align__(256) float g_h2[NN * HH];
__device__ __align__(256) float g_agg[NN * HH];
__device__ __align__(256) float g_maxp[GG * HH];
__device__ __align__(256) float g_sump[GG * HH];
__device__ __align__(256) float g_cnt[GG];
__device__ int g_is64;

// ---------------- dtype detection ----------------
// edge ids are < 2^31. If the buffer is int64 (little-endian), every odd
// 32-bit word is the zero high-half. If int32, odd words are random node ids
// in [0,100000) -> probability all 128 samples are zero ~ 1e-640.
__global__ void detect_kernel(const unsigned* __restrict__ raw) {
    if (threadIdx.x == 0) {
        int any = 0;
        #pragma unroll 4
        for (int i = 1; i < 256; i += 2) any |= (raw[i] != 0u);
        g_is64 = (any == 0);
    }
}

__device__ __forceinline__ int load_idx(const void* p, long long i) {
    if (g_is64) return (int)((const long long*)p)[i];
    return ((const int*)p)[i];
}

// ---------------- zero kernels ----------------
__global__ void zero_agg_kernel(int n_elem) {
    int i = blockIdx.x * blockDim.x + threadIdx.x;
    if (i < n_elem) g_agg[i] = 0.0f;
}

__global__ void zero_pool_kernel() {
    int i = blockIdx.x * blockDim.x + threadIdx.x;
    if (i < GG * HH) { g_maxp[i] = 0.0f; g_sump[i] = 0.0f; }
    if (i < GG) g_cnt[i] = 0.0f;
}

// ---------------- edge scatter: g_agg[dst] += hin[src] ----------------
template <int DIN>
__global__ void scatter_kernel(const float* __restrict__ hin,
                               const void* __restrict__ ei, int nE) {
    int e = blockIdx.x * blockDim.x + threadIdx.x;
    if (e >= nE) return;
    int s = load_idx(ei, e);
    int d = load_idx(ei, (long long)nE + e);
    const float* xr = hin + (long long)s * DIN;
    float* ar = g_agg + (long long)d * DIN;
    if (DIN == 20) {
        #pragma unroll
        for (int i = 0; i < 5; i++) {
            float4 v = *(const float4*)(xr + 4 * i);
            asm volatile("red.global.add.v4.f32 [%0], {%1,%2,%3,%4};"
                         :: "l"(ar + 4 * i), "f"(v.x), "f"(v.y), "f"(v.z), "f"(v.w)
                         : "memory");
        }
    } else {
        #pragma unroll
        for (int i = 0; i < 5; i++) {
            float2 v = *(const float2*)(xr + 2 * i);
            asm volatile("red.global.add.v2.f32 [%0], {%1,%2};"
                         :: "l"(ar + 2 * i), "f"(v.x), "f"(v.y)
                         : "memory");
        }
    }
}

// ---------------- node update: hout = relu(agg @ Wrel + b + hin @ Wroot) ----
template <int DIN>
__global__ void node_kernel(const float* __restrict__ hin,
                            const float* __restrict__ Wrel,
                            const float* __restrict__ b,
                            const float* __restrict__ Wroot,
                            float* __restrict__ hout, int n) {
    __shared__ float sWrel[DIN * HH];
    __shared__ float sWroot[DIN * HH];
    __shared__ float sb[HH];
    int t = threadIdx.x;
    for (int i = t; i < DIN * HH; i += blockDim.x) {
        sWrel[i] = Wrel[i];
        sWroot[i] = Wroot[i];
    }
    if (t < HH) sb[t] = b[t];
    __syncthreads();
    int i = blockIdx.x * blockDim.x + t;
    if (i >= n) return;

    float acc[HH];
    #pragma unroll
    for (int j = 0; j < HH; j++) acc[j] = sb[j];

    const float* ar = g_agg + (long long)i * DIN;
    const float* xr = hin + (long long)i * DIN;
    #pragma unroll
    for (int k = 0; k < DIN; k++) {
        float a = ar[k];
        float r = xr[k];
        #pragma unroll
        for (int j = 0; j < HH; j++)
            acc[j] += a * sWrel[k * HH + j] + r * sWroot[k * HH + j];
    }
    float* o = hout + (long long)i * HH;
    #pragma unroll
    for (int j = 0; j < HH; j++) o[j] = fmaxf(acc[j], 0.0f);
}

// ---------------- pooling: per-graph max / sum / count ----------------
__global__ void pool_kernel(const float* __restrict__ h,
                            const void* __restrict__ batch, int n) {
    int i = blockIdx.x * blockDim.x + threadIdx.x;
    if (i >= n) return;
    int g = load_idx(batch, i);
    const float* r = h + (long long)i * HH;
    atomicAdd(&g_cnt[g], 1.0f);
    #pragma unroll
    for (int j = 0; j < HH; j++) {
        float v = r[j];
        atomicAdd(&g_sump[g * HH + j], v);
        // v >= 0 after relu -> uint bit-pattern ordering == float ordering
        atomicMax((unsigned*)&g_maxp[g * HH + j], __float_as_uint(v));
    }
}

// ---------------- readout: out = [maxp, meanp] @ W_lin + b_lin ----------
__global__ void readout_kernel(const float* __restrict__ Wlin,
                               const float* __restrict__ blin,
                               float* __restrict__ out, int ng) {
    int g = blockIdx.x * blockDim.x + threadIdx.x;
    if (g >= ng) return;
    float cnt = fmaxf(g_cnt[g], 1.0f);
    float inv = 1.0f / cnt;
    float o0 = blin[0], o1 = blin[1];
    #pragma unroll
    for (int j = 0; j < HH; j++) {
        float mx = g_maxp[g * HH + j];
        float mn = g_sump[g * HH + j] * inv;
        o0 += mx * Wlin[j * 2 + 0] + mn * Wlin[(HH + j) * 2 + 0];
        o1 += mx * Wlin[j * 2 + 1] + mn * Wlin[(HH + j) * 2 + 1];
    }
    out[g * 2 + 0] = o0;
    out[g * 2 + 1] = o1;
}

// ---------------- launcher ----------------
extern "C" void kernel_launch(void* const* d_in, const int* in_sizes, int n_in,
                              void* d_out, int out_size) {
    const float* x      = (const float*)d_in[0];
    const void*  ei     = d_in[1];
    const void*  batch  = d_in[2];
    const float* Wrel1  = (const float*)d_in[3];
    const float* b1     = (const float*)d_in[4];
    const float* Wroot1 = (const float*)d_in[5];
    const float* Wrel2  = (const float*)d_in[6];
    const float* b2     = (const float*)d_in[7];
    const float* Wroot2 = (const float*)d_in[8];
    const float* Wrel3  = (const float*)d_in[9];
    const float* b3     = (const float*)d_in[10];
    const float* Wroot3 = (const float*)d_in[11];
    const float* Wlin   = (const float*)d_in[12];
    const float* blin   = (const float*)d_in[13];

    const int n  = in_sizes[0] / FF;     // nodes
    const int nE = in_sizes[1] / 2;      // edges
    const int ng = out_size / 2;         // graphs

    detect_kernel<<<1, 32>>>((const unsigned*)ei);
    zero_pool_kernel<<<(GG * HH + 255) / 256, 256>>>();

    const int EB = (nE + 255) / 256;
    const int NB128 = (n + 127) / 128;

    // layer 1: F=10 -> H=20
    zero_agg_kernel<<<(n * FF + 255) / 256, 256>>>(n * FF);
    scatter_kernel<FF><<<EB, 256>>>(x, ei, nE);
    node_kernel<FF><<<NB128, 128>>>(x, Wrel1, b1, Wroot1, g_h1, n);

    // layer 2: H -> H
    zero_agg_kernel<<<(n * HH + 255) / 256, 256>>>(n * HH);
    scatter_kernel<HH><<<EB, 256>>>(g_h1, ei, nE);
    node_kernel<HH><<<NB128, 128>>>(g_h1, Wrel2, b2, Wroot2, g_h2, n);

    // layer 3: H -> H
    zero_agg_kernel<<<(n * HH + 255) / 256, 256>>>(n * HH);
    scatter_kernel<HH><<<EB, 256>>>(g_h2, ei, nE);
    node_kernel<HH><<<NB128, 128>>>(g_h2, Wrel3, b3, Wroot3, g_h1, n);

    // pooling + readout
    pool_kernel<<<(n + 255) / 256, 256>>>(g_h1, batch, n);
    readout_kernel<<<(ng + 255) / 256, 256>>>(Wlin, blin, (float*)d_out, ng);
}

// round 2
// speedup vs baseline: 1.0843x; 1.0843x over previous
#include <cuda_runtime.h>
#include <cstdint>

#define NN 100000
#define EE 3200000
#define FF 10
#define HH 20
#define GG 512

// ---------------- device scratch (no allocation allowed) ----------------
__device__ __align__(256) float g_h1[NN * HH];
__device__ __align__(256) float g_h2[NN * HH];
__device__ __align__(256) float g_agg[NN * HH];
__device__ __align__(256) float g_maxp[GG * HH];
__device__ __align__(256) float g_sump[GG * HH];
__device__ __align__(256) float g_cnt[GG];
__device__ int g_is64;

// ---------------- dtype detection ----------------
// edge ids are < 2^31. If the buffer is int64 (little-endian), every odd
// 32-bit word is a zero high-half. If int32, odd words are random node ids
// in [0,100000) -> P(all 128 samples zero) ~ 1e-640.
__global__ void detect_kernel(const unsigned* __restrict__ raw) {
    if (threadIdx.x == 0) {
        int any = 0;
        #pragma unroll 4
        for (int i = 1; i < 256; i += 2) any |= (raw[i] != 0u);
        g_is64 = (any == 0);
    }
}

__device__ __forceinline__ int load_idx(const void* p, long long i) {
    if (g_is64) return (int)((const long long*)p)[i];
    return ((const int*)p)[i];
}

// ---------------- zero kernel ----------------
__global__ void zero_agg_kernel(int n_elem) {
    int i = blockIdx.x * blockDim.x + threadIdx.x;
    if (i < n_elem) g_agg[i] = 0.0f;
}

// ---------------- edge scatter: g_agg[dst] += hin[src] ----------------
// v2 REDs only: the v2 path is measured at the native LTS fp32-atomic
// roofline; v4 REDs are the suspected slow (emulated) path.
template <int DIN>
__global__ void scatter_kernel(const float* __restrict__ hin,
                               const void* __restrict__ ei, int nE) {
    int e = blockIdx.x * blockDim.x + threadIdx.x;
    if (e >= nE) return;
    int s = load_idx(ei, e);
    int d = load_idx(ei, (long long)nE + e);
    const float* xr = hin + (long long)s * DIN;
    float* ar = g_agg + (long long)d * DIN;
    #pragma unroll
    for (int i = 0; i < DIN / 2; i++) {
        float2 v = *(const float2*)(xr + 2 * i);
        asm volatile("red.global.add.v2.f32 [%0], {%1,%2};"
                     :: "l"(ar + 2 * i), "f"(v.x), "f"(v.y)
                     : "memory");
    }
}

// ---------------- node update: hout = relu(agg @ Wrel + b + hin @ Wroot) ----
template <int DIN>
__global__ void __launch_bounds__(128)
node_kernel(const float* __restrict__ hin,
            const float* __restrict__ Wrel,
            const float* __restrict__ b,
            const float* __restrict__ Wroot,
            float* __restrict__ hout, int n) {
    __shared__ float sWrel[DIN * HH];
    __shared__ float sWroot[DIN * HH];
    __shared__ float sb[HH];
    int t = threadIdx.x;
    for (int i = t; i < DIN * HH; i += blockDim.x) {
        sWrel[i] = Wrel[i];
        sWroot[i] = Wroot[i];
    }
    if (t < HH) sb[t] = b[t];
    __syncthreads();
    int i = blockIdx.x * blockDim.x + t;
    if (i >= n) return;

    float acc[HH];
    #pragma unroll
    for (int j = 0; j < HH; j++) acc[j] = sb[j];

    const float* ar = g_agg + (long long)i * DIN;
    const float* xr = hin + (long long)i * DIN;
    #pragma unroll
    for (int k = 0; k < DIN; k++) {
        float a = ar[k];
        float r = xr[k];
        #pragma unroll
        for (int j = 0; j < HH; j++)
            acc[j] += a * sWrel[k * HH + j] + r * sWroot[k * HH + j];
    }
    float* o = hout + (long long)i * HH;
    #pragma unroll
    for (int j = 0; j < HH; j++) o[j] = fmaxf(acc[j], 0.0f);
}

// ---------------- pooling: warp per graph, batch is sorted -> segments ----
__global__ void __launch_bounds__(32)
pool_kernel(const float* __restrict__ h, const void* __restrict__ batch,
            int n) {
    int g = blockIdx.x;
    int lane = threadIdx.x;

    // binary search segment bounds (all lanes redundantly; converged control)
    int lo = 0, hi = n;
    while (lo < hi) {
        int mid = (lo + hi) >> 1;
        if (load_idx(batch, mid) < g) lo = mid + 1; else hi = mid;
    }
    int start = lo;
    hi = n;
    while (lo < hi) {
        int mid = (lo + hi) >> 1;
        if (load_idx(batch, mid) <= g) lo = mid + 1; else hi = mid;
    }
    int end = lo;

    if (lane < HH) {
        float mx = 0.0f;   // relu(h) >= 0: 0-init == where(nonempty, max, 0)
        float sm = 0.0f;
        const float* p = h + (long long)start * HH + lane;
        int cnt = end - start;
        int i = 0;
        #pragma unroll 4
        for (; i + 4 <= cnt; i += 4) {
            float v0 = p[(long long)(i + 0) * HH];
            float v1 = p[(long long)(i + 1) * HH];
            float v2 = p[(long long)(i + 2) * HH];
            float v3 = p[(long long)(i + 3) * HH];
            mx = fmaxf(mx, fmaxf(fmaxf(v0, v1), fmaxf(v2, v3)));
            sm += (v0 + v1) + (v2 + v3);
        }
        for (; i < cnt; i++) {
            float v = p[(long long)i * HH];
            mx = fmaxf(mx, v);
            sm += v;
        }
        g_maxp[g * HH + lane] = mx;
        g_sump[g * HH + lane] = sm;
    }
    if (lane == 0) g_cnt[g] = (float)(end - start);
}

// ---------------- readout: out = [maxp, meanp] @ W_lin + b_lin ----------
__global__ void readout_kernel(const float* __restrict__ Wlin,
                               const float* __restrict__ blin,
                               float* __restrict__ out, int ng) {
    int g = blockIdx.x * blockDim.x + threadIdx.x;
    if (g >= ng) return;
    float cnt = fmaxf(g_cnt[g], 1.0f);
    float inv = 1.0f / cnt;
    float o0 = blin[0], o1 = blin[1];
    #pragma unroll
    for (int j = 0; j < HH; j++) {
        float mx = g_maxp[g * HH + j];
        float mn = g_sump[g * HH + j] * inv;
        o0 += mx * Wlin[j * 2 + 0] + mn * Wlin[(HH + j) * 2 + 0];
        o1 += mx * Wlin[j * 2 + 1] + mn * Wlin[(HH + j) * 2 + 1];
    }
    out[g * 2 + 0] = o0;
    out[g * 2 + 1] = o1;
}

// ---------------- launcher ----------------
extern "C" void kernel_launch(void* const* d_in, const int* in_sizes, int n_in,
                              void* d_out, int out_size) {
    const float* x      = (const float*)d_in[0];
    const void*  ei     = d_in[1];
    const void*  batch  = d_in[2];
    const float* Wrel1  = (const float*)d_in[3];
    const float* b1     = (const float*)d_in[4];
    const float* Wroot1 = (const float*)d_in[5];
    const float* Wrel2  = (const float*)d_in[6];
    const float* b2     = (const float*)d_in[7];
    const float* Wroot2 = (const float*)d_in[8];
    const float* Wrel3  = (const float*)d_in[9];
    const float* b3     = (const float*)d_in[10];
    const float* Wroot3 = (const float*)d_in[11];
    const float* Wlin   = (const float*)d_in[12];
    const float* blin   = (const float*)d_in[13];

    const int n  = in_sizes[0] / FF;     // nodes
    const int nE = in_sizes[1] / 2;      // edges
    const int ng = out_size / 2;         // graphs

    detect_kernel<<<1, 32>>>((const unsigned*)ei);

    const int EB = (nE + 255) / 256;
    const int NB128 = (n + 127) / 128;

    // layer 1: F=10 -> H=20
    zero_agg_kernel<<<(n * FF + 255) / 256, 256>>>(n * FF);
    scatter_kernel<FF><<<EB, 256>>>(x, ei, nE);
    node_kernel<FF><<<NB128, 128>>>(x, Wrel1, b1, Wroot1, g_h1, n);

    // layer 2: H -> H
    zero_agg_kernel<<<(n * HH + 255) / 256, 256>>>(n * HH);
    scatter_kernel<HH><<<EB, 256>>>(g_h1, ei, nE);
    node_kernel<HH><<<NB128, 128>>>(g_h1, Wrel2, b2, Wroot2, g_h2, n);

    // layer 3: H -> H
    zero_agg_kernel<<<(n * HH + 255) / 256, 256>>>(n * HH);
    scatter_kernel<HH><<<EB, 256>>>(g_h2, ei, nE);
    node_kernel<HH><<<NB128, 128>>>(g_h2, Wrel3, b3, Wroot3, g_h1, n);

    // pooling (atomic-free, warp per graph) + readout
    pool_kernel<<<ng, 32>>>(g_h1, batch, n);
    readout_kernel<<<(ng + 255) / 256, 256>>>(Wlin, blin, (float*)d_out, ng);
}

// round 3
// speedup vs baseline: 8.6420x; 7.9700x over previous
#include <cuda_runtime.h>
#include <cstdint>

#define NN 100000
#define FF 10
#define HH 20

#define NBLK 148
#define NTHR 512
#define NT   (NBLK * NTHR)

// ---------------- device scratch (no allocation allowed) ----------------
__device__ __align__(256) float g_h1[NN * HH];
__device__ __align__(256) float g_h2[NN * HH];
__device__ __align__(256) float g_agg1[NN * FF];
__device__ __align__(256) float g_agg2[NN * HH];
__device__ __align__(256) float g_agg3[NN * HH];
__device__ unsigned g_bar_count;            // zero-init; self-resetting
__device__ volatile unsigned g_bar_gen;     // monotonic across launches

// ---------------- software grid barrier (all blocks co-resident) -------
__device__ __forceinline__ void grid_sync() {
    __syncthreads();
    if (threadIdx.x == 0) {
        __threadfence();                      // make prior stores/REDs visible
        unsigned gen = g_bar_gen;
        if (atomicAdd(&g_bar_count, 1u) == NBLK - 1) {
            g_bar_count = 0;
            __threadfence();
            g_bar_gen = gen + 1;
        } else {
            while (g_bar_gen == gen) __nanosleep(64);
        }
        __threadfence();                      // acquire
    }
    __syncthreads();
}

// ---------------- scatter: agg[dst] += hin[src], v2 REDs ----------------
template <int DIN>
__device__ __forceinline__ void scat_row(const float* __restrict__ xr,
                                         float* __restrict__ ar) {
    #pragma unroll
    for (int i = 0; i < DIN / 2; i++) {
        float2 v = *(const float2*)(xr + 2 * i);
        asm volatile("red.global.add.v2.f32 [%0], {%1,%2};"
                     :: "l"(ar + 2 * i), "f"(v.x), "f"(v.y)
                     : "memory");
    }
}

template <int DIN>
__device__ void scatter_phase(const float* __restrict__ hin,
                              const void* __restrict__ ei, int nE,
                              float* __restrict__ agg, bool is64, int gtid) {
    if (is64) {
        const long long* e = (const long long*)ei;
        for (int k = gtid; k < nE; k += NT) {
            int s = (int)e[k];
            int d = (int)e[nE + k];
            scat_row<DIN>(hin + (long long)s * DIN, agg + (long long)d * DIN);
        }
    } else {
        const int* e = (const int*)ei;
        for (int k = gtid; k < nE; k += NT) {
            int s = e[k];
            int d = e[nE + k];
            scat_row<DIN>(hin + (long long)s * DIN, agg + (long long)d * DIN);
        }
    }
}

// ---------------- node update: hout = relu(agg @ Wrel + b + hin @ Wroot) --
template <int DIN>
__device__ void node_phase(const float* __restrict__ hin,
                           const float* __restrict__ agg,
                           const float* __restrict__ Wrel,
                           const float* __restrict__ b,
                           const float* __restrict__ Wroot,
                           float* __restrict__ hout, int n,
                           float* __restrict__ sW, int gtid) {
    float* sWrel  = sW;
    float* sWroot = sW + DIN * HH;
    float* sb     = sW + 2 * DIN * HH;
    for (int i = threadIdx.x; i < DIN * HH; i += NTHR) {
        sWrel[i]  = Wrel[i];
        sWroot[i] = Wroot[i];
    }
    if (threadIdx.x < HH) sb[threadIdx.x] = b[threadIdx.x];
    __syncthreads();

    for (int i = gtid; i < n; i += NT) {
        float acc[HH];
        #pragma unroll
        for (int j = 0; j < HH; j++) acc[j] = sb[j];
        const float* ar = agg + (long long)i * DIN;
        const float* xr = hin + (long long)i * DIN;
        #pragma unroll
        for (int k = 0; k < DIN; k++) {
            float a = ar[k];
            float r = xr[k];
            #pragma unroll
            for (int j = 0; j < HH; j++)
                acc[j] += a * sWrel[k * HH + j] + r * sWroot[k * HH + j];
        }
        float* o = hout + (long long)i * HH;
        #pragma unroll
        for (int j = 0; j < HH; j++) o[j] = fmaxf(acc[j], 0.0f);
    }
}

// ---------------- pool + readout fused: warp per graph ------------------
__device__ __forceinline__ int bidx(const void* p, int i, bool is64) {
    return is64 ? (int)((const long long*)p)[i] : ((const int*)p)[i];
}

__device__ void pool_readout_phase(const float* __restrict__ h,
                                   const void* __restrict__ batch, bool is64,
                                   const float* __restrict__ Wlin,
                                   const float* __restrict__ blin,
                                   float* __restrict__ out, int n, int ng,
                                   int gtid) {
    int w = gtid >> 5;           // global warp id == graph id
    int lane = threadIdx.x & 31;
    if (w >= ng) return;         // last phase: early return is safe

    // binary search segment [start, end) of graph w (batch is sorted)
    int lo = 0, hi = n;
    while (lo < hi) {
        int mid = (lo + hi) >> 1;
        if (bidx(batch, mid, is64) < w) lo = mid + 1; else hi = mid;
    }
    int start = lo;
    hi = n;
    while (lo < hi) {
        int mid = (lo + hi) >> 1;
        if (bidx(batch, mid, is64) <= w) lo = mid + 1; else hi = mid;
    }
    int end = lo;
    int cnt = end - start;

    float mx = 0.0f, sm = 0.0f;  // relu(h) >= 0 -> 0-init max matches ref
    if (lane < HH) {
        const float* p = h + (long long)start * HH + lane;
        int i = 0;
        for (; i + 4 <= cnt; i += 4) {
            float v0 = p[(long long)(i + 0) * HH];
            float v1 = p[(long long)(i + 1) * HH];
            float v2 = p[(long long)(i + 2) * HH];
            float v3 = p[(long long)(i + 3) * HH];
            mx = fmaxf(mx, fmaxf(fmaxf(v0, v1), fmaxf(v2, v3)));
            sm += (v0 + v1) + (v2 + v3);
        }
        for (; i < cnt; i++) {
            float v = p[(long long)i * HH];
            mx = fmaxf(mx, v);
            sm += v;
        }
    }
    float mean = sm / fmaxf((float)cnt, 1.0f);

    float c0 = 0.0f, c1 = 0.0f;
    if (lane < HH) {
        c0 = mx * Wlin[lane * 2 + 0] + mean * Wlin[(HH + lane) * 2 + 0];
        c1 = mx * Wlin[lane * 2 + 1] + mean * Wlin[(HH + lane) * 2 + 1];
    }
    #pragma unroll
    for (int off = 16; off > 0; off >>= 1) {
        c0 += __shfl_down_sync(0xFFFFFFFFu, c0, off);
        c1 += __shfl_down_sync(0xFFFFFFFFu, c1, off);
    }
    if (lane == 0) {
        out[w * 2 + 0] = c0 + blin[0];
        out[w * 2 + 1] = c1 + blin[1];
    }
}

// ---------------- the single fused persistent kernel --------------------
__global__ void __launch_bounds__(NTHR, 1)
fused_kernel(const float* __restrict__ x,
             const void* __restrict__ ei,
             const void* __restrict__ batch,
             const float* __restrict__ Wrel1, const float* __restrict__ b1,
             const float* __restrict__ Wroot1,
             const float* __restrict__ Wrel2, const float* __restrict__ b2,
             const float* __restrict__ Wroot2,
             const float* __restrict__ Wrel3, const float* __restrict__ b3,
             const float* __restrict__ Wroot3,
             const float* __restrict__ Wlin, const float* __restrict__ blin,
             float* __restrict__ out, int n, int nE, int ng) {
    __shared__ float sW[2 * HH * HH + HH];
    int gtid = blockIdx.x * NTHR + threadIdx.x;

    // dtype detect: int64 edge ids have zero high words; int32 ids don't.
    // P(false positive) ~ (1/2^32)^128 per block.
    unsigned odd = 0;
    if (threadIdx.x < 128) odd = ((const unsigned*)ei)[2 * threadIdx.x + 1];
    bool is64 = (__syncthreads_or(odd != 0u) == 0);

    // phase A: zero all agg buffers
    for (int i = gtid; i < n * FF; i += NT) g_agg1[i] = 0.0f;
    for (int i = gtid; i < n * HH; i += NT) { g_agg2[i] = 0.0f; g_agg3[i] = 0.0f; }
    grid_sync();

    // layer 1: F=10 -> H=20
    scatter_phase<FF>(x, ei, nE, g_agg1, is64, gtid);
    grid_sync();
    node_phase<FF>(x, g_agg1, Wrel1, b1, Wroot1, g_h1, n, sW, gtid);
    grid_sync();

    // layer 2: H -> H
    scatter_phase<HH>(g_h1, ei, nE, g_agg2, is64, gtid);
    grid_sync();
    node_phase<HH>(g_h1, g_agg2, Wrel2, b2, Wroot2, g_h2, n, sW, gtid);
    grid_sync();

    // layer 3: H -> H
    scatter_phase<HH>(g_h2, ei, nE, g_agg3, is64, gtid);
    grid_sync();
    node_phase<HH>(g_h2, g_agg3, Wrel3, b3, Wroot3, g_h1, n, sW, gtid);
    grid_sync();

    // pool + readout (fused, atomic-free)
    pool_readout_phase(g_h1, batch, is64, Wlin, blin, out, n, ng, gtid);
}

// ---------------- launcher: ONE kernel launch ----------------------------
extern "C" void kernel_launch(void* const* d_in, const int* in_sizes, int n_in,
                              void* d_out, int out_size) {
    const float* x      = (const float*)d_in[0];
    const void*  ei     = d_in[1];
    const void*  batch  = d_in[2];
    const float* Wrel1  = (const float*)d_in[3];
    const float* b1     = (const float*)d_in[4];
    const float* Wroot1 = (const float*)d_in[5];
    const float* Wrel2  = (const float*)d_in[6];
    const float* b2     = (const float*)d_in[7];
    const float* Wroot2 = (const float*)d_in[8];
    const float* Wrel3  = (const float*)d_in[9];
    const float* b3     = (const float*)d_in[10];
    const float* Wroot3 = (const float*)d_in[11];
    const float* Wlin   = (const float*)d_in[12];
    const float* blin   = (const float*)d_in[13];

    const int n  = in_sizes[0] / FF;     // nodes
    const int nE = in_sizes[1] / 2;      // edges
    const int ng = out_size / 2;         // graphs

    fused_kernel<<<NBLK, NTHR>>>(x, ei, batch,
                                 Wrel1, b1, Wroot1,
                                 Wrel2, b2, Wroot2,
                                 Wrel3, b3, Wroot3,
                                 Wlin, blin, (float*)d_out, n, nE, ng);
}

// round 5
// speedup vs baseline: 20.8626x; 2.4141x over previous
#include <cuda_runtime.h>
#include <cstdint>

#define NN 100000
#define EE 3200000
#define FF 10
#define HH 20

#define NBLK 148
#define NTHR 512
#define NT   (NBLK * NTHR)

// ---------------- device scratch (no allocation allowed) ----------------
__device__ __align__(256) float g_h1[NN * HH];
__device__ __align__(256) float g_h2[NN * HH];
__device__ __align__(256) int   g_row_ptr[NN + 1];
__device__ __align__(256) int   g_cursor[NN];
__device__ __align__(256) int   g_hist[NN];
__device__ __align__(256) int   g_col[EE];
__device__ __align__(256) int   g_bsum[NBLK];
__device__ unsigned g_bar_count;            // zero-init; self-resetting
__device__ volatile unsigned g_bar_gen;     // monotonic across launches

// ---------------- software grid barrier (all blocks co-resident) -------
__device__ __forceinline__ void grid_sync() {
    __syncthreads();
    if (threadIdx.x == 0) {
        __threadfence();
        unsigned gen = g_bar_gen;
        if (atomicAdd(&g_bar_count, 1u) == NBLK - 1) {
            g_bar_count = 0;
            __threadfence();
            g_bar_gen = gen + 1;
        } else {
            while (g_bar_gen == gen) __nanosleep(64);
        }
        __threadfence();
    }
    __syncthreads();
}

// ---------------- gather + node update fused ----------------------------
// out[i] = relu( (sum_{e: dst=i} hin[col[e]]) @ Wrel + b + hin[i] @ Wroot )
template <int DIN>
__device__ void layer_phase(const float* __restrict__ hin,
                            const float* __restrict__ Wrel,
                            const float* __restrict__ b,
                            const float* __restrict__ Wroot,
                            float* __restrict__ hout, int n,
                            float* __restrict__ sW, int gtid) {
    float* sWrel  = sW;
    float* sWroot = sW + DIN * HH;
    float* sb     = sW + 2 * DIN * HH;
    for (int i = threadIdx.x; i < DIN * HH; i += NTHR) {
        sWrel[i]  = Wrel[i];
        sWroot[i] = Wroot[i];
    }
    if (threadIdx.x < HH) sb[threadIdx.x] = b[threadIdx.x];
    __syncthreads();

    for (int i = gtid; i < n; i += NT) {
        int beg = g_row_ptr[i];
        int end = g_row_ptr[i + 1];
        float acc[DIN];
        #pragma unroll
        for (int k = 0; k < DIN; k++) acc[k] = 0.0f;

        for (int e = beg; e < end; e++) {
            int s = g_col[e];
            const float* r = hin + (long long)s * DIN;
            if (DIN % 4 == 0) {
                // row is 16B-aligned for any s (DIN*4 % 16 == 0)
                #pragma unroll
                for (int q = 0; q < DIN / 4; q++) {
                    float4 v = *(const float4*)(r + 4 * q);
                    acc[4 * q + 0] += v.x;
                    acc[4 * q + 1] += v.y;
                    acc[4 * q + 2] += v.z;
                    acc[4 * q + 3] += v.w;
                }
            } else {
                // DIN=10: rows only 8B-aligned -> float2 loads
                #pragma unroll
                for (int q = 0; q < DIN / 2; q++) {
                    float2 v = *(const float2*)(r + 2 * q);
                    acc[2 * q + 0] += v.x;
                    acc[2 * q + 1] += v.y;
                }
            }
        }

        float o[HH];
        #pragma unroll
        for (int j = 0; j < HH; j++) o[j] = sb[j];
        #pragma unroll
        for (int k = 0; k < DIN; k++) {
            float a = acc[k];
            #pragma unroll
            for (int j = 0; j < HH; j++) o[j] += a * sWrel[k * HH + j];
        }
        const float* xr = hin + (long long)i * DIN;
        #pragma unroll
        for (int k = 0; k < DIN; k++) {
            float r = xr[k];
            #pragma unroll
            for (int j = 0; j < HH; j++) o[j] += r * sWroot[k * HH + j];
        }
        float* op = hout + (long long)i * HH;
        #pragma unroll
        for (int j = 0; j < HH; j++) op[j] = fmaxf(o[j], 0.0f);
    }
}

// ---------------- pool + readout fused: warp per graph ------------------
__device__ __forceinline__ int bidx(const void* p, int i, bool is64) {
    return is64 ? (int)((const long long*)p)[i] : ((const int*)p)[i];
}

__device__ void pool_readout_phase(const float* __restrict__ h,
                                   const void* __restrict__ batch, bool is64,
                                   const float* __restrict__ Wlin,
                                   const float* __restrict__ blin,
                                   float* __restrict__ out, int n, int ng,
                                   int gtid) {
    int w = gtid >> 5;
    int lane = threadIdx.x & 31;
    if (w >= ng) return;

    int lo = 0, hi = n;
    while (lo < hi) {
        int mid = (lo + hi) >> 1;
        if (bidx(batch, mid, is64) < w) lo = mid + 1; else hi = mid;
    }
    int start = lo;
    hi = n;
    while (lo < hi) {
        int mid = (lo + hi) >> 1;
        if (bidx(batch, mid, is64) <= w) lo = mid + 1; else hi = mid;
    }
    int cnt = lo - start;

    float mx = 0.0f, sm = 0.0f;   // relu >= 0: 0-init max matches reference
    if (lane < HH) {
        const float* p = h + (long long)start * HH + lane;
        int i = 0;
        for (; i + 4 <= cnt; i += 4) {
            float v0 = p[(long long)(i + 0) * HH];
            float v1 = p[(long long)(i + 1) * HH];
            float v2 = p[(long long)(i + 2) * HH];
            float v3 = p[(long long)(i + 3) * HH];
            mx = fmaxf(mx, fmaxf(fmaxf(v0, v1), fmaxf(v2, v3)));
            sm += (v0 + v1) + (v2 + v3);
        }
        for (; i < cnt; i++) {
            float v = p[(long long)i * HH];
            mx = fmaxf(mx, v);
            sm += v;
        }
    }
    float mean = sm / fmaxf((float)cnt, 1.0f);

    float c0 = 0.0f, c1 = 0.0f;
    if (lane < HH) {
        c0 = mx * Wlin[lane * 2 + 0] + mean * Wlin[(HH + lane) * 2 + 0];
        c1 = mx * Wlin[lane * 2 + 1] + mean * Wlin[(HH + lane) * 2 + 1];
    }
    #pragma unroll
    for (int off = 16; off > 0; off >>= 1) {
        c0 += __shfl_down_sync(0xFFFFFFFFu, c0, off);
        c1 += __shfl_down_sync(0xFFFFFFFFu, c1, off);
    }
    if (lane == 0) {
        out[w * 2 + 0] = c0 + blin[0];
        out[w * 2 + 1] = c1 + blin[1];
    }
}

// ---------------- the single fused persistent kernel --------------------
__global__ void __launch_bounds__(NTHR, 1)
fused_kernel(const float* __restrict__ x,
             const void* __restrict__ ei,
             const void* __restrict__ batch,
             const float* __restrict__ Wrel1, const float* __restrict__ b1,
             const float* __restrict__ Wroot1,
             const float* __restrict__ Wrel2, const float* __restrict__ b2,
             const float* __restrict__ Wroot2,
             const float* __restrict__ Wrel3, const float* __restrict__ b3,
             const float* __restrict__ Wroot3,
             const float* __restrict__ Wlin, const float* __restrict__ blin,
             float* __restrict__ out, int n, int nE, int ng) {
    __shared__ float sW[2 * HH * HH + HH];
    __shared__ int s_wsum[NTHR / 32];
    __shared__ int s_boff;
    int t = threadIdx.x;
    int gtid = blockIdx.x * NTHR + t;
    int lane = t & 31;
    int wid = t >> 5;

    // dtype detect: int64 ids have zero high words; P(FP) ~ 2^-4096.
    unsigned oddw = 0;
    if (t < 128) oddw = ((const unsigned*)ei)[2 * t + 1];
    bool is64 = (__syncthreads_or(oddw != 0u) == 0);

    // ---- phase 0: zero histogram ----
    for (int i = gtid; i < n; i += NT) g_hist[i] = 0;
    grid_sync();

    // ---- phase 1: in-degree histogram over dst ----
    if (is64) {
        const long long* e = (const long long*)ei;
        for (int k = gtid; k < nE; k += NT)
            atomicAdd(&g_hist[(int)e[nE + k]], 1);
    } else {
        const int* e = (const int*)ei;
        for (int k = gtid; k < nE; k += NT)
            atomicAdd(&g_hist[e[nE + k]], 1);
    }
    grid_sync();

    // ---- phase 2: per-block exclusive scan of chunk; block sums out ----
    int chunk = (n + NBLK - 1) / NBLK;          // 676 for n=100000 (<=1024)
    int base = blockIdx.x * chunk;
    {
        int i0 = 2 * t, i1 = 2 * t + 1;
        int v0 = (i0 < chunk && base + i0 < n) ? g_hist[base + i0] : 0;
        int v1 = (i1 < chunk && base + i1 < n) ? g_hist[base + i1] : 0;
        int ts = v0 + v1;
        // warp inclusive scan
        int sc = ts;
        #pragma unroll
        for (int off = 1; off < 32; off <<= 1) {
            int u = __shfl_up_sync(0xFFFFFFFFu, sc, off);
            if (lane >= off) sc += u;
        }
        if (lane == 31) s_wsum[wid] = sc;
        __syncthreads();
        if (wid == 0) {
            int ws = (lane < NTHR / 32) ? s_wsum[lane] : 0;
            int wsc = ws;
            #pragma unroll
            for (int off = 1; off < 32; off <<= 1) {
                int u = __shfl_up_sync(0xFFFFFFFFu, wsc, off);
                if (lane >= off) wsc += u;
            }
            if (lane < NTHR / 32) s_wsum[lane] = wsc - ws;  // exclusive
            if (lane == NTHR / 32 - 1) g_bsum[blockIdx.x] = wsc;
        }
        __syncthreads();
        int excl = s_wsum[wid] + (sc - ts);                 // thread exclusive
        if (i0 < chunk && base + i0 < n) g_row_ptr[base + i0] = excl;
        if (i1 < chunk && base + i1 < n) g_row_ptr[base + i1] = excl + v0;
    }
    grid_sync();

    // ---- phase 3: add block offset, init cursor ----
    {
        if (t == 0) {
            int off = 0;
            for (int bb = 0; bb < (int)blockIdx.x; bb++) off += g_bsum[bb];
            s_boff = off;
            if (blockIdx.x == 0) g_row_ptr[n] = nE;
        }
        __syncthreads();
        int boff = s_boff;
        for (int i = t; i < chunk; i += NTHR) {
            int gi = base + i;
            if (gi < n) {
                int v = g_row_ptr[gi] + boff;
                g_row_ptr[gi] = v;
                g_cursor[gi] = v;
            }
        }
    }
    grid_sync();

    // ---- phase 4: fill col (CSR by dst, values = src) ----
    if (is64) {
        const long long* e = (const long long*)ei;
        for (int k = gtid; k < nE; k += NT) {
            int s = (int)e[k];
            int d = (int)e[nE + k];
            g_col[atomicAdd(&g_cursor[d], 1)] = s;
        }
    } else {
        const int* e = (const int*)ei;
        for (int k = gtid; k < nE; k += NT) {
            int s = e[k];
            int d = e[nE + k];
            g_col[atomicAdd(&g_cursor[d], 1)] = s;
        }
    }
    grid_sync();

    // ---- layers: gather + dense update fused ----
    layer_phase<FF>(x,    Wrel1, b1, Wroot1, g_h1, n, sW, gtid);
    grid_sync();
    layer_phase<HH>(g_h1, Wrel2, b2, Wroot2, g_h2, n, sW, gtid);
    grid_sync();
    layer_phase<HH>(g_h2, Wrel3, b3, Wroot3, g_h1, n, sW, gtid);
    grid_sync();

    // ---- pool + readout ----
    pool_readout_phase(g_h1, batch, is64, Wlin, blin, out, n, ng, gtid);
}

// ---------------- launcher: ONE kernel launch ----------------------------
extern "C" void kernel_launch(void* const* d_in, const int* in_sizes, int n_in,
                              void* d_out, int out_size) {
    const float* x      = (const float*)d_in[0];
    const void*  ei     = d_in[1];
    const void*  batch  = d_in[2];
    const float* Wrel1  = (const float*)d_in[3];
    const float* b1     = (const float*)d_in[4];
    const float* Wroot1 = (const float*)d_in[5];
    const float* Wrel2  = (const float*)d_in[6];
    const float* b2     = (const float*)d_in[7];
    const float* Wroot2 = (const float*)d_in[8];
    const float* Wrel3  = (const float*)d_in[9];
    const float* b3     = (const float*)d_in[10];
    const float* Wroot3 = (const float*)d_in[11];
    const float* Wlin   = (const float*)d_in[12];
    const float* blin   = (const float*)d_in[13];

    const int n  = in_sizes[0] / FF;
    const int nE = in_sizes[1] / 2;
    const int ng = out_size / 2;

    fused_kernel<<<NBLK, NTHR>>>(x, ei, batch,
                                 Wrel1, b1, Wroot1,
                                 Wrel2, b2, Wroot2,
                                 Wrel3, b3, Wroot3,
                                 Wlin, blin, (float*)d_out, n, nE, ng);
}